// round 4
// baseline (speedup 1.0000x reference)
#include <cuda_runtime.h>
#include <cuda_fp16.h>
#include <cstdint>
#include <cstddef>

#define HID 128
#define NMAX 100000
#define MMAX 800000
#define CMAX 1024
#define NCMAX 1000
#define CH 512

__device__ int    g_deg[NMAX];
__device__ int    g_rowstart[NMAX + 1];
__device__ int    g_pos[NMAX];
__device__ float  g_invdeg[NMAX];
__device__ int    g_csr[MMAX];
__device__ float  g_h[(size_t)NMAX * HID];
__device__ float  g_agg[(size_t)NMAX * HID];
__device__ float  g_base[NCMAX * HID];
__device__ float  g_part[512 * HID];
__device__ float  g_ge[HID];
__device__ float  g_ce[CMAX * HID];
__device__ __half g_slab[(size_t)CMAX * NCMAX * HID];

__device__ __forceinline__ float gelu_f(float x) {
    return 0.5f * x * (1.0f + erff(x * 0.70710678f));
}
__device__ __forceinline__ float wred(float v) {
    #pragma unroll
    for (int o = 16; o; o >>= 1) v += __shfl_xor_sync(0xffffffffu, v, o);
    return v;
}

// ---------------- graph prep ----------------
__global__ void k_zero(int N) {
    int i = blockIdx.x * blockDim.x + threadIdx.x;
    if (i < N) g_deg[i] = 0;
}
__global__ void k_deg(const int* __restrict__ ei, int M) {
    int e = blockIdx.x * blockDim.x + threadIdx.x;
    if (e < M) atomicAdd(&g_deg[ei[M + e]], 1);
}
__global__ void k_scan(int N) {
    __shared__ int s[1024];
    __shared__ int carry;
    int t = threadIdx.x;
    if (t == 0) { carry = 0; g_rowstart[0] = 0; }
    __syncthreads();
    int nch = (N + 1023) >> 10;
    for (int ch = 0; ch < nch; ++ch) {
        int i = (ch << 10) + t;
        s[t] = (i < N) ? g_deg[i] : 0;
        __syncthreads();
        for (int off = 1; off < 1024; off <<= 1) {
            int add = (t >= off) ? s[t - off] : 0;
            __syncthreads();
            s[t] += add;
            __syncthreads();
        }
        if (i < N) g_rowstart[i + 1] = carry + s[t];
        __syncthreads();
        if (t == 0) carry += s[1023];
        __syncthreads();
    }
}
__global__ void k_posinv(int N) {
    int i = blockIdx.x * blockDim.x + threadIdx.x;
    if (i < N) {
        g_pos[i] = g_rowstart[i];
        int d = g_deg[i];
        g_invdeg[i] = 1.0f / (float)(d > 0 ? d : 1);
    }
}
__global__ void k_scatter(const int* __restrict__ ei, int M) {
    int e = blockIdx.x * blockDim.x + threadIdx.x;
    if (e < M) {
        int dst = ei[M + e];
        int slot = atomicAdd(&g_pos[dst], 1);
        g_csr[slot] = ei[e];
    }
}

// ---------------- input embed: x@in_w + LN + GELU ----------------
__global__ void k_input(const float* __restrict__ feat, const int* __restrict__ opcode,
                        const float* __restrict__ depth, const float* __restrict__ emb,
                        const float* __restrict__ W, const float* __restrict__ b,
                        const float* __restrict__ lg, const float* __restrict__ lb, int N) {
    __shared__ float xs[4][208];
    __shared__ float part[4][4];
    int tid = threadIdx.x, lane = tid & 31, wid = tid >> 5;
    int n0 = blockIdx.x * 4;
    #pragma unroll
    for (int j = 0; j < 4; ++j) {
        int n = n0 + j;
        if (n >= N) n = N - 1;  // duplicate last node; store is guarded below
        for (int i = tid; i < 140; i += 128) xs[j][i] = feat[(size_t)n * 140 + i];
        if (tid < 64) {
            int op = opcode[n]; op = op < 0 ? 0 : (op > 119 ? 119 : op);
            xs[j][140 + tid] = emb[op * 64 + tid];
        }
        if (tid == 0) xs[j][204] = depth[n];
    }
    __syncthreads();
    int col = tid;
    float acc[4];
    #pragma unroll
    for (int j = 0; j < 4; ++j) acc[j] = b[col];
    for (int k = 0; k < 205; ++k) {
        float w = W[k * HID + col];
        #pragma unroll
        for (int j = 0; j < 4; ++j) acc[j] += xs[j][k] * w;
    }
    // LN per node over 128 cols
    float mu[4], iv[4];
    #pragma unroll
    for (int j = 0; j < 4; ++j) {
        float r = wred(acc[j]);
        if (lane == 0) part[j][wid] = r;
    }
    __syncthreads();
    #pragma unroll
    for (int j = 0; j < 4; ++j) mu[j] = (part[j][0] + part[j][1] + part[j][2] + part[j][3]) * (1.f / HID);
    __syncthreads();
    #pragma unroll
    for (int j = 0; j < 4; ++j) {
        float d = acc[j] - mu[j];
        float r = wred(d * d);
        if (lane == 0) part[j][wid] = r;
    }
    __syncthreads();
    #pragma unroll
    for (int j = 0; j < 4; ++j) iv[j] = rsqrtf((part[j][0] + part[j][1] + part[j][2] + part[j][3]) * (1.f / HID) + 1e-5f);
    float gg = lg[col], bb = lb[col];
    #pragma unroll
    for (int j = 0; j < 4; ++j) {
        int n = n0 + j;
        if (n < N) g_h[(size_t)n * HID + col] = gelu_f((acc[j] - mu[j]) * iv[j] * gg + bb);
    }
}

// ---------------- mean aggregation: warp per node ----------------
__global__ void k_agg(int N) {
    int gw = (blockIdx.x * blockDim.x + threadIdx.x) >> 5;
    int lane = threadIdx.x & 31;
    if (gw >= N) return;
    int rs = g_rowstart[gw], re = g_rowstart[gw + 1];
    float4 acc = make_float4(0.f, 0.f, 0.f, 0.f);
    for (int e = rs; e < re; ++e) {
        int s = g_csr[e];
        float4 v = *(const float4*)&g_h[(size_t)s * HID + lane * 4];
        acc.x += v.x; acc.y += v.y; acc.z += v.z; acc.w += v.w;
    }
    float idg = g_invdeg[gw];
    acc.x *= idg; acc.y *= idg; acc.z *= idg; acc.w *= idg;
    *(float4*)&g_agg[(size_t)gw * HID + lane * 4] = acc;
}

// ---------------- SAGE layer: conv + residual + LN ----------------
__global__ void k_layer(const float* __restrict__ Wl, const float* __restrict__ bl,
                        const float* __restrict__ Wr, const float* __restrict__ lg,
                        const float* __restrict__ lb, int N) {
    __shared__ float s[4][2 * HID];
    __shared__ float part[4][4];
    int tid = threadIdx.x, lane = tid & 31, wid = tid >> 5;
    int n0 = blockIdx.x * 4;
    #pragma unroll
    for (int j = 0; j < 4; ++j) {
        int n = n0 + j < N ? n0 + j : N - 1;
        s[j][tid] = g_agg[(size_t)n * HID + tid];
        s[j][HID + tid] = g_h[(size_t)n * HID + tid];
    }
    __syncthreads();
    int col = tid;
    float acc[4];
    #pragma unroll
    for (int j = 0; j < 4; ++j) acc[j] = bl[col];
    for (int k = 0; k < HID; ++k) {
        float w = Wl[k * HID + col];
        #pragma unroll
        for (int j = 0; j < 4; ++j) acc[j] += s[j][k] * w;
    }
    for (int k = 0; k < HID; ++k) {
        float w = Wr[k * HID + col];
        #pragma unroll
        for (int j = 0; j < 4; ++j) acc[j] += s[j][HID + k] * w;
    }
    float r[4];
    #pragma unroll
    for (int j = 0; j < 4; ++j) r[j] = s[j][HID + col] + gelu_f(acc[j]);
    float mu[4], iv[4];
    #pragma unroll
    for (int j = 0; j < 4; ++j) {
        float t = wred(r[j]);
        if (lane == 0) part[j][wid] = t;
    }
    __syncthreads();
    #pragma unroll
    for (int j = 0; j < 4; ++j) mu[j] = (part[j][0] + part[j][1] + part[j][2] + part[j][3]) * (1.f / HID);
    __syncthreads();
    #pragma unroll
    for (int j = 0; j < 4; ++j) {
        float d = r[j] - mu[j];
        float t = wred(d * d);
        if (lane == 0) part[j][wid] = t;
    }
    __syncthreads();
    #pragma unroll
    for (int j = 0; j < 4; ++j) iv[j] = rsqrtf((part[j][0] + part[j][1] + part[j][2] + part[j][3]) * (1.f / HID) + 1e-5f);
    float gg = lg[col], bb = lb[col];
    #pragma unroll
    for (int j = 0; j < 4; ++j) {
        int n = n0 + j;
        if (n < N) g_h[(size_t)n * HID + col] = (r[j] - mu[j]) * iv[j] * gg + bb;
    }
}

// ---------------- global mean of h (deterministic 2-stage) ----------------
__global__ void k_gmean1(int N) {
    int col = threadIdx.x, blk = blockIdx.x;
    int per = (N + 511) / 512;
    int n0 = blk * per, n1 = n0 + per; if (n1 > N) n1 = N;
    float acc = 0.f;
    for (int n = n0; n < n1; ++n) acc += g_h[(size_t)n * HID + col];
    g_part[blk * HID + col] = acc;
}
__global__ void k_gmean2(int N) {
    int col = threadIdx.x;
    float acc = 0.f;
    for (int b = 0; b < 512; ++b) acc += g_part[b * HID + col];
    g_ge[col] = acc / (float)N;
}

// ---------------- base[nc] = h[cfg_id[nc]] @ cfg_w[:128] + cfg_b ----------------
__global__ void k_base(const int* __restrict__ ids, const float* __restrict__ W,
                       const float* __restrict__ b, int NC) {
    __shared__ float row[HID];
    int nc = blockIdx.x, col = threadIdx.x;
    int nd = ids[nc];
    row[col] = g_h[(size_t)nd * HID + col];
    __syncthreads();
    float acc = b[col];
    for (int k = 0; k < HID; ++k) acc += row[k] * W[k * HID + col];
    g_base[nc * HID + col] = acc;
}

// ---------------- scoring: proj + SE + chunk softmax, 1 block = (chunk, nc) ----------------
__global__ void k_score(const float* __restrict__ cfgf, const float* __restrict__ cfg_w,
                        const float* __restrict__ w1, const float* __restrict__ b1,
                        const float* __restrict__ w2s, const float* __restrict__ b2,
                        const float* __restrict__ temp, int C, int NC) {
    extern __shared__ unsigned char sm[];
    __half* projs = (__half*)sm;                       // 512*128
    float* base_s = (float*)(sm + CH * HID * 2);       // 128
    float* w18 = base_s + HID;                         // 18*128
    float* sw1 = w18 + 18 * HID;                       // 128*16
    float* sw2 = sw1 + HID * 16;                       // 16*128
    float* sb1 = sw2 + 16 * HID;                       // 16
    float* sb2 = sb1 + 16;                             // 128
    int tid = threadIdx.x;
    int chunk = blockIdx.x, nc = blockIdx.y;
    for (int i = tid; i < 18 * HID; i += CH) w18[i] = cfg_w[128 * HID + i];
    for (int i = tid; i < HID * 16; i += CH) sw1[i] = w1[i];
    for (int i = tid; i < 16 * HID; i += CH) sw2[i] = w2s[i];
    if (tid < 16) sb1[tid] = b1[tid];
    if (tid < HID) sb2[tid] = b2[tid];
    if (tid < HID) base_s[tid] = g_base[nc * HID + tid];
    __syncthreads();
    int c = tid;                 // local config in chunk
    int cg = chunk * CH + c;     // global config
    float f[18];
    #pragma unroll
    for (int j = 0; j < 18; ++j) f[j] = cfgf[((size_t)cg * NC + nc) * 18 + j];
    float s1[16];
    #pragma unroll
    for (int r = 0; r < 16; ++r) s1[r] = sb1[r];
    for (int col = 0; col < HID; ++col) {
        float v = base_s[col];
        #pragma unroll
        for (int j = 0; j < 18; ++j) v += f[j] * w18[j * HID + col];
        v = gelu_f(v);
        projs[col * CH + c] = __float2half(v);
        #pragma unroll
        for (int r = 0; r < 16; ++r) s1[r] += v * sw1[col * 16 + r];
    }
    #pragma unroll
    for (int r = 0; r < 16; ++r) s1[r] = fmaxf(s1[r], 0.f);
    for (int col = 0; col < HID; ++col) {
        float z = sb2[col];
        #pragma unroll
        for (int r = 0; r < 16; ++r) z += s1[r] * sw2[r * HID + col];
        float scale = 1.f / (1.f + __expf(-z));
        float v = __half2float(projs[col * CH + c]) * scale;
        projs[col * CH + c] = __float2half(v);
    }
    __syncthreads();
    // softmax over the 512 configs per column; 16 warps x 8 cols
    float invT = 1.f / temp[0];
    int lane = tid & 31, wid = tid >> 5;
    for (int ci = 0; ci < 8; ++ci) {
        int col = wid + ci * 16;
        float v[16], m = -1e30f;
        #pragma unroll
        for (int i = 0; i < 16; ++i) {
            v[i] = __half2float(projs[col * CH + lane + i * 32]);
            m = fmaxf(m, v[i]);
        }
        #pragma unroll
        for (int o = 16; o; o >>= 1) m = fmaxf(m, __shfl_xor_sync(0xffffffffu, m, o));
        float se = 0.f;
        #pragma unroll
        for (int i = 0; i < 16; ++i) se += __expf((v[i] - m) * invT);
        se = wred(se);
        float inv_se = 1.f / se;
        #pragma unroll
        for (int i = 0; i < 16; ++i) {
            float w = __expf((v[i] - m) * invT) * inv_se;
            projs[col * CH + lane + i * 32] = __float2half(v[i] * w);
        }
    }
    __syncthreads();
    // coalesced spill to slab
    for (int i = tid; i < CH * HID; i += CH) {
        int cl = i >> 7, col = i & 127;
        g_slab[((size_t)(chunk * CH + cl) * NC + nc) * HID + col] = projs[col * CH + cl];
    }
}

// ---------------- slab reduce: config_embeds = mean over nc ----------------
__global__ void k_reduce(int C, int NC) {
    int c = blockIdx.x, col = threadIdx.x;
    float acc = 0.f;
    const __half* p = &g_slab[(size_t)c * NC * HID + col];
    for (int nc = 0; nc < NC; ++nc) acc += __half2float(p[(size_t)nc * HID]);
    g_ce[c * HID + col] = acc / (float)NC;
}

// ---------------- head MLP ----------------
__global__ void k_head(const float* __restrict__ w1, const float* __restrict__ b1,
                       const float* __restrict__ w2, const float* __restrict__ b2,
                       const float* __restrict__ w3, const float* __restrict__ b3,
                       float* __restrict__ out, int N, int C) {
    __shared__ float ges[HID], ces[HID], x1[HID], x2[64];
    int c = blockIdx.x, col = threadIdx.x;
    ges[col] = g_ge[col];
    ces[col] = g_ce[c * HID + col];
    __syncthreads();
    float acc = b1[col];
    for (int k = 0; k < HID; ++k) acc += ges[k] * w1[k * HID + col];
    for (int k = 0; k < HID; ++k) acc += ces[k] * w1[(HID + k) * HID + col];
    x1[col] = gelu_f(acc);
    __syncthreads();
    if (col < 64) {
        float a2 = b2[col];
        for (int k = 0; k < HID; ++k) a2 += x1[k] * w2[k * 64 + col];
        x2[col] = gelu_f(a2);
    }
    __syncthreads();
    if (col == 0) {
        float s = b3[0];
        for (int k = 0; k < 64; ++k) s += x2[k] * w3[k];
        out[c] = s;
    }
}

extern "C" void kernel_launch(void* const* d_in, const int* in_sizes, int n_in,
                              void* d_out, int out_size) {
    const float* node_feat = (const float*)d_in[0];
    const int*   node_opc  = (const int*)d_in[1];
    const float* topo      = (const float*)d_in[2];
    const int*   ei        = (const int*)d_in[3];
    const int*   cfg_ids   = (const int*)d_in[4];
    const float* cfg_feat  = (const float*)d_in[5];
    const float* temp      = (const float*)d_in[6];
    const float* opc_emb   = (const float*)d_in[7];
    const float* in_w      = (const float*)d_in[8];
    const float* in_b      = (const float*)d_in[9];
    const float* in_g      = (const float*)d_in[10];
    const float* in_beta   = (const float*)d_in[11];
    const float* sage_Wl   = (const float*)d_in[12];
    const float* sage_bl   = (const float*)d_in[13];
    const float* sage_Wr   = (const float*)d_in[14];
    const float* ln_g      = (const float*)d_in[15];
    const float* ln_b      = (const float*)d_in[16];
    const float* cfg_w     = (const float*)d_in[17];
    const float* cfg_b     = (const float*)d_in[18];
    const float* se_w1     = (const float*)d_in[19];
    const float* se_b1     = (const float*)d_in[20];
    const float* se_w2     = (const float*)d_in[21];
    const float* se_b2     = (const float*)d_in[22];
    const float* h_w1      = (const float*)d_in[23];
    const float* h_b1      = (const float*)d_in[24];
    const float* h_w2      = (const float*)d_in[25];
    const float* h_b2      = (const float*)d_in[26];
    const float* h_w3      = (const float*)d_in[27];
    const float* h_b3      = (const float*)d_in[28];

    int N  = in_sizes[1];
    int M  = in_sizes[3] / 2;
    int NC = in_sizes[4];
    int C  = in_sizes[5] / (NC * 18);
    int chunks = C / CH;

    k_zero<<<(N + 255) / 256, 256>>>(N);
    k_input<<<(N + 3) / 4, 128>>>(node_feat, node_opc, topo, opc_emb,
                                  in_w, in_b, in_g, in_beta, N);
    k_deg<<<(M + 255) / 256, 256>>>(ei, M);
    k_scan<<<1, 1024>>>(N);
    k_posinv<<<(N + 255) / 256, 256>>>(N);
    k_scatter<<<(M + 255) / 256, 256>>>(ei, M);
    for (int l = 0; l < 4; ++l) {
        k_agg<<<(N + 7) / 8, 256>>>(N);
        k_layer<<<(N + 3) / 4, 128>>>(sage_Wl + (size_t)l * HID * HID,
                                      sage_bl + l * HID,
                                      sage_Wr + (size_t)l * HID * HID,
                                      ln_g + l * HID, ln_b + l * HID, N);
    }
    k_gmean1<<<512, 128>>>(N);
    k_gmean2<<<1, 128>>>(N);
    k_base<<<NC, 128>>>(cfg_ids, cfg_w, cfg_b, NC);

    size_t score_smem = (size_t)CH * HID * 2 +
                        (HID + 18 * HID + HID * 16 + 16 * HID + 16 + HID) * sizeof(float);
    cudaFuncSetAttribute(k_score, cudaFuncAttributeMaxDynamicSharedMemorySize, (int)score_smem);
    dim3 sg(chunks, NC);
    k_score<<<sg, CH, score_smem>>>(cfg_feat, cfg_w, se_w1, se_b1, se_w2, se_b2,
                                    temp, C, NC);
    k_reduce<<<C, 128>>>(C, NC);
    k_head<<<C, 128>>>(h_w1, h_b1, h_w2, h_b2, h_w3, h_b3, (float*)d_out, N, C);
}

// round 5
// speedup vs baseline: 1.3170x; 1.3170x over previous
#include <cuda_runtime.h>
#include <cuda_fp16.h>
#include <cstdint>
#include <cstddef>

#define HID 128
#define NMAX 100000
#define MMAX 800000
#define CMAX 1024
#define NCMAX 1000
#define CH 512
#define XSTR 68   // smem row stride (floats) for transposed x tiles

__device__ int    g_deg[NMAX];
__device__ int    g_rowstart[NMAX + 1];
__device__ int    g_pos[NMAX];
__device__ float  g_invdeg[NMAX];
__device__ int    g_csr[MMAX];
__device__ int    g_bsum[128];
__device__ int    g_boff[128];
__device__ float  g_h[(size_t)NMAX * HID];
__device__ float  g_agg[(size_t)NMAX * HID];
__device__ float  g_base[NCMAX * HID];
__device__ float  g_partial[512 * HID];
__device__ float  g_ge[HID];
__device__ float  g_ce[CMAX * HID];
__device__ __half g_slab[(size_t)CMAX * NCMAX * HID];

__device__ __forceinline__ float gelu_f(float x) {
    return 0.5f * x * (1.0f + erff(x * 0.70710678f));
}
__device__ __forceinline__ float wred(float v) {
    #pragma unroll
    for (int o = 16; o; o >>= 1) v += __shfl_xor_sync(0xffffffffu, v, o);
    return v;
}

// ---------------- graph prep ----------------
__global__ void k_zero(int N) {
    int i = blockIdx.x * blockDim.x + threadIdx.x;
    if (i < N) g_deg[i] = 0;
}
__global__ void k_deg(const int* __restrict__ ei, int M) {
    int e = blockIdx.x * blockDim.x + threadIdx.x;
    if (e < M) atomicAdd(&g_deg[ei[M + e]], 1);
}
__global__ void k_scan1(int N) {
    __shared__ int s[1024];
    int t = threadIdx.x, i = blockIdx.x * 1024 + t;
    s[t] = (i < N) ? g_deg[i] : 0;
    __syncthreads();
    for (int o = 1; o < 1024; o <<= 1) {
        int a = (t >= o) ? s[t - o] : 0;
        __syncthreads();
        s[t] += a;
        __syncthreads();
    }
    if (i < N) g_rowstart[i + 1] = s[t];
    if (t == 1023) g_bsum[blockIdx.x] = s[1023];
}
__global__ void k_scan2(int nb) {
    if (threadIdx.x == 0) {
        int run = 0;
        for (int b = 0; b < nb; ++b) { g_boff[b] = run; run += g_bsum[b]; }
    }
}
__global__ void k_scan3(int N) {
    int i = blockIdx.x * blockDim.x + threadIdx.x;
    if (i == 0) g_rowstart[0] = 0;
    if (i < N) g_rowstart[i + 1] += g_boff[i >> 10];
}
__global__ void k_posinv(int N) {
    int i = blockIdx.x * blockDim.x + threadIdx.x;
    if (i < N) {
        g_pos[i] = g_rowstart[i];
        int d = g_deg[i];
        g_invdeg[i] = 1.0f / (float)(d > 0 ? d : 1);
    }
}
__global__ void k_scatter(const int* __restrict__ ei, int M) {
    int e = blockIdx.x * blockDim.x + threadIdx.x;
    if (e < M) {
        int dst = ei[M + e];
        int slot = atomicAdd(&g_pos[dst], 1);
        g_csr[slot] = ei[e];
    }
}

// ---------------- input embed: 64 nodes x 128 cols tiled GEMM + LN + GELU ----------------
__global__ void k_input(const float* __restrict__ feat, const int* __restrict__ opcode,
                        const float* __restrict__ depth, const float* __restrict__ emb,
                        const float* __restrict__ W, const float* __restrict__ b,
                        const float* __restrict__ lg, const float* __restrict__ lb, int N) {
    extern __shared__ float xs[];   // [205][XSTR] transposed: xs[k*XSTR + n]
    int tid = threadIdx.x, lane = tid & 31, wp = tid >> 5;
    int n0 = blockIdx.x * 64;
    for (int i = tid; i < 64 * 140; i += 256) {
        int n = i / 140, k = i - n * 140;
        int gn = n0 + n; if (gn >= N) gn = N - 1;
        xs[k * XSTR + n] = feat[(size_t)gn * 140 + k];
    }
    for (int i = tid; i < 64 * 64; i += 256) {
        int n = i >> 6, k = i & 63;
        int gn = n0 + n; if (gn >= N) gn = N - 1;
        int op = opcode[gn]; op = op < 0 ? 0 : (op > 119 ? 119 : op);
        xs[(140 + k) * XSTR + n] = emb[op * 64 + k];
    }
    if (tid < 64) {
        int gn = n0 + tid; if (gn >= N) gn = N - 1;
        xs[204 * XSTR + tid] = depth[gn];
    }
    __syncthreads();

    int ng = wp;              // node group: 8 nodes
    int c0 = lane * 4;        // 4 cols
    float4 acc[8];
    #pragma unroll
    for (int j = 0; j < 8; ++j) acc[j] = make_float4(0.f, 0.f, 0.f, 0.f);
    #pragma unroll 4
    for (int k = 0; k < 205; ++k) {
        float4 w4 = *(const float4*)&W[k * HID + c0];
        const float4* xp = (const float4*)&xs[k * XSTR + ng * 8];
        float4 xa = xp[0], xb = xp[1];
        float xv[8] = {xa.x, xa.y, xa.z, xa.w, xb.x, xb.y, xb.z, xb.w};
        #pragma unroll
        for (int j = 0; j < 8; ++j) {
            acc[j].x += xv[j] * w4.x; acc[j].y += xv[j] * w4.y;
            acc[j].z += xv[j] * w4.z; acc[j].w += xv[j] * w4.w;
        }
    }
    float4 b4 = *(const float4*)&b[c0];
    float4 g4 = *(const float4*)&lg[c0];
    float4 e4 = *(const float4*)&lb[c0];
    float mu[8], iv[8];
    #pragma unroll
    for (int j = 0; j < 8; ++j) {
        acc[j].x += b4.x; acc[j].y += b4.y; acc[j].z += b4.z; acc[j].w += b4.w;
        mu[j] = wred(acc[j].x + acc[j].y + acc[j].z + acc[j].w) * (1.f / HID);
    }
    #pragma unroll
    for (int j = 0; j < 8; ++j) {
        float dx = acc[j].x - mu[j], dy = acc[j].y - mu[j];
        float dz = acc[j].z - mu[j], dw = acc[j].w - mu[j];
        iv[j] = rsqrtf(wred(dx * dx + dy * dy + dz * dz + dw * dw) * (1.f / HID) + 1e-5f);
    }
    #pragma unroll
    for (int j = 0; j < 8; ++j) {
        int gn = n0 + ng * 8 + j;
        if (gn < N) {
            float4 o;
            o.x = gelu_f((acc[j].x - mu[j]) * iv[j] * g4.x + e4.x);
            o.y = gelu_f((acc[j].y - mu[j]) * iv[j] * g4.y + e4.y);
            o.z = gelu_f((acc[j].z - mu[j]) * iv[j] * g4.z + e4.z);
            o.w = gelu_f((acc[j].w - mu[j]) * iv[j] * g4.w + e4.w);
            *(float4*)&g_h[(size_t)gn * HID + c0] = o;
        }
    }
}

// ---------------- mean aggregation: warp per node ----------------
__global__ void k_agg(int N) {
    int gw = (blockIdx.x * blockDim.x + threadIdx.x) >> 5;
    int lane = threadIdx.x & 31;
    if (gw >= N) return;
    int rs = g_rowstart[gw], re = g_rowstart[gw + 1];
    float4 acc = make_float4(0.f, 0.f, 0.f, 0.f);
    for (int e = rs; e < re; ++e) {
        int s = g_csr[e];
        float4 v = *(const float4*)&g_h[(size_t)s * HID + lane * 4];
        acc.x += v.x; acc.y += v.y; acc.z += v.z; acc.w += v.w;
    }
    float idg = g_invdeg[gw];
    acc.x *= idg; acc.y *= idg; acc.z *= idg; acc.w *= idg;
    *(float4*)&g_agg[(size_t)gw * HID + lane * 4] = acc;
}

// ---------------- SAGE layer: 64 nodes x 128 cols tiled GEMM + residual + LN ----------------
__global__ void k_layer(const float* __restrict__ Wl, const float* __restrict__ bl,
                        const float* __restrict__ Wr, const float* __restrict__ lg,
                        const float* __restrict__ lb, int N) {
    extern __shared__ float xs[];   // [256][XSTR]: rows 0..127 agg, 128..255 h
    int tid = threadIdx.x, lane = tid & 31, wp = tid >> 5;
    int n0 = blockIdx.x * 64;
    for (int i = tid; i < 64 * 128; i += 256) {
        int n = i >> 7, k = i & 127;
        int gn = n0 + n; if (gn >= N) gn = N - 1;
        xs[k * XSTR + n] = g_agg[(size_t)gn * HID + k];
        xs[(128 + k) * XSTR + n] = g_h[(size_t)gn * HID + k];
    }
    __syncthreads();

    int ng = wp, c0 = lane * 4;
    float4 acc[8];
    #pragma unroll
    for (int j = 0; j < 8; ++j) acc[j] = make_float4(0.f, 0.f, 0.f, 0.f);
    #pragma unroll 4
    for (int k = 0; k < 128; ++k) {
        float4 w4 = *(const float4*)&Wl[k * HID + c0];
        const float4* xp = (const float4*)&xs[k * XSTR + ng * 8];
        float4 xa = xp[0], xb = xp[1];
        float xv[8] = {xa.x, xa.y, xa.z, xa.w, xb.x, xb.y, xb.z, xb.w};
        #pragma unroll
        for (int j = 0; j < 8; ++j) {
            acc[j].x += xv[j] * w4.x; acc[j].y += xv[j] * w4.y;
            acc[j].z += xv[j] * w4.z; acc[j].w += xv[j] * w4.w;
        }
    }
    #pragma unroll 4
    for (int k = 0; k < 128; ++k) {
        float4 w4 = *(const float4*)&Wr[k * HID + c0];
        const float4* xp = (const float4*)&xs[(128 + k) * XSTR + ng * 8];
        float4 xa = xp[0], xb = xp[1];
        float xv[8] = {xa.x, xa.y, xa.z, xa.w, xb.x, xb.y, xb.z, xb.w};
        #pragma unroll
        for (int j = 0; j < 8; ++j) {
            acc[j].x += xv[j] * w4.x; acc[j].y += xv[j] * w4.y;
            acc[j].z += xv[j] * w4.z; acc[j].w += xv[j] * w4.w;
        }
    }
    float4 b4 = *(const float4*)&bl[c0];
    float4 g4 = *(const float4*)&lg[c0];
    float4 e4 = *(const float4*)&lb[c0];
    float mu[8], iv[8];
    #pragma unroll
    for (int j = 0; j < 8; ++j) {
        int gn = n0 + ng * 8 + j; int cg = gn < N ? gn : N - 1;
        float4 hv = *(const float4*)&g_h[(size_t)cg * HID + c0];
        acc[j].x = hv.x + gelu_f(acc[j].x + b4.x);
        acc[j].y = hv.y + gelu_f(acc[j].y + b4.y);
        acc[j].z = hv.z + gelu_f(acc[j].z + b4.z);
        acc[j].w = hv.w + gelu_f(acc[j].w + b4.w);
        mu[j] = wred(acc[j].x + acc[j].y + acc[j].z + acc[j].w) * (1.f / HID);
    }
    #pragma unroll
    for (int j = 0; j < 8; ++j) {
        float dx = acc[j].x - mu[j], dy = acc[j].y - mu[j];
        float dz = acc[j].z - mu[j], dw = acc[j].w - mu[j];
        iv[j] = rsqrtf(wred(dx * dx + dy * dy + dz * dz + dw * dw) * (1.f / HID) + 1e-5f);
    }
    __syncthreads();   // all xs h-reads done before overwriting g_h (same-block safety)
    #pragma unroll
    for (int j = 0; j < 8; ++j) {
        int gn = n0 + ng * 8 + j;
        if (gn < N) {
            float4 o;
            o.x = (acc[j].x - mu[j]) * iv[j] * g4.x + e4.x;
            o.y = (acc[j].y - mu[j]) * iv[j] * g4.y + e4.y;
            o.z = (acc[j].z - mu[j]) * iv[j] * g4.z + e4.z;
            o.w = (acc[j].w - mu[j]) * iv[j] * g4.w + e4.w;
            *(float4*)&g_h[(size_t)gn * HID + c0] = o;
        }
    }
}

// ---------------- global mean of h (deterministic 2-stage) ----------------
__global__ void k_gmean1(int N) {
    int col = threadIdx.x, blk = blockIdx.x;
    int per = (N + 511) / 512;
    int a = blk * per, b = a + per; if (b > N) b = N;
    float acc = 0.f;
    for (int n = a; n < b; ++n) acc += g_h[(size_t)n * HID + col];
    g_partial[blk * HID + col] = acc;
}
__global__ void k_gmean2(int N) {
    int col = threadIdx.x;
    float acc = 0.f;
    for (int b = 0; b < 512; ++b) acc += g_partial[b * HID + col];
    g_ge[col] = acc / (float)N;
}

// ---------------- base[nc] = h[cfg_id[nc]] @ cfg_w[:128] + cfg_b ----------------
__global__ void k_base(const int* __restrict__ ids, const float* __restrict__ W,
                       const float* __restrict__ b, int NC) {
    __shared__ float row[HID];
    int nc = blockIdx.x, col = threadIdx.x;
    int nd = ids[nc];
    row[col] = g_h[(size_t)nd * HID + col];
    __syncthreads();
    float acc = b[col];
    for (int k = 0; k < HID; ++k) acc += row[k] * W[k * HID + col];
    g_base[nc * HID + col] = acc;
}

// ---------------- scoring: proj + SE + chunk softmax, 1 block = (chunk, nc) ----------------
__global__ void k_score(const float* __restrict__ cfgf, const float* __restrict__ cfg_w,
                        const float* __restrict__ w1, const float* __restrict__ b1,
                        const float* __restrict__ w2s, const float* __restrict__ b2,
                        const float* __restrict__ temp, int C, int NC) {
    extern __shared__ unsigned char sm[];
    __half* projs = (__half*)sm;                       // 512*128
    float* base_s = (float*)(sm + CH * HID * 2);       // 128
    float* w18 = base_s + HID;                         // 18*128
    float* sw1 = w18 + 18 * HID;                       // 128*16
    float* sw2 = sw1 + HID * 16;                       // 16*128
    float* sb1 = sw2 + 16 * HID;                       // 16
    float* sb2 = sb1 + 16;                             // 128
    int tid = threadIdx.x;
    int chunk = blockIdx.x, nc = blockIdx.y;
    for (int i = tid; i < 18 * HID; i += CH) w18[i] = cfg_w[128 * HID + i];
    for (int i = tid; i < HID * 16; i += CH) sw1[i] = w1[i];
    for (int i = tid; i < 16 * HID; i += CH) sw2[i] = w2s[i];
    if (tid < 16) sb1[tid] = b1[tid];
    if (tid < HID) sb2[tid] = b2[tid];
    if (tid < HID) base_s[tid] = g_base[nc * HID + tid];
    __syncthreads();
    int c = tid;
    int cg = chunk * CH + c;
    float f[18];
    #pragma unroll
    for (int j = 0; j < 18; ++j) f[j] = cfgf[((size_t)cg * NC + nc) * 18 + j];
    float s1[16];
    #pragma unroll
    for (int r = 0; r < 16; ++r) s1[r] = sb1[r];
    for (int col = 0; col < HID; ++col) {
        float v = base_s[col];
        #pragma unroll
        for (int j = 0; j < 18; ++j) v += f[j] * w18[j * HID + col];
        v = gelu_f(v);
        projs[col * CH + c] = __float2half(v);
        #pragma unroll
        for (int r = 0; r < 16; ++r) s1[r] += v * sw1[col * 16 + r];
    }
    #pragma unroll
    for (int r = 0; r < 16; ++r) s1[r] = fmaxf(s1[r], 0.f);
    for (int col = 0; col < HID; ++col) {
        float z = sb2[col];
        #pragma unroll
        for (int r = 0; r < 16; ++r) z += s1[r] * sw2[r * HID + col];
        float scale = 1.f / (1.f + __expf(-z));
        float v = __half2float(projs[col * CH + c]) * scale;
        projs[col * CH + c] = __float2half(v);
    }
    __syncthreads();
    float invT = 1.f / temp[0];
    int lane = tid & 31, wid = tid >> 5;
    for (int ci = 0; ci < 8; ++ci) {
        int col = wid + ci * 16;
        float v[16], m = -1e30f;
        #pragma unroll
        for (int i = 0; i < 16; ++i) {
            v[i] = __half2float(projs[col * CH + lane + i * 32]);
            m = fmaxf(m, v[i]);
        }
        #pragma unroll
        for (int o = 16; o; o >>= 1) m = fmaxf(m, __shfl_xor_sync(0xffffffffu, m, o));
        float se = 0.f;
        #pragma unroll
        for (int i = 0; i < 16; ++i) se += __expf((v[i] - m) * invT);
        se = wred(se);
        float inv_se = 1.f / se;
        #pragma unroll
        for (int i = 0; i < 16; ++i) {
            float w = __expf((v[i] - m) * invT) * inv_se;
            projs[col * CH + lane + i * 32] = __float2half(v[i] * w);
        }
    }
    __syncthreads();
    for (int i = tid; i < CH * HID; i += CH) {
        int cl = i >> 7, col = i & 127;
        g_slab[((size_t)(chunk * CH + cl) * NC + nc) * HID + col] = projs[col * CH + cl];
    }
}

// ---------------- slab reduce: config_embeds = mean over nc ----------------
__global__ void k_reduce(int C, int NC) {
    int c = blockIdx.x, col = threadIdx.x;
    float acc = 0.f;
    const __half* p = &g_slab[(size_t)c * NC * HID + col];
    for (int nc = 0; nc < NC; ++nc) acc += __half2float(p[(size_t)nc * HID]);
    g_ce[c * HID + col] = acc / (float)NC;
}

// ---------------- head MLP ----------------
__global__ void k_head(const float* __restrict__ w1, const float* __restrict__ b1,
                       const float* __restrict__ w2, const float* __restrict__ b2,
                       const float* __restrict__ w3, const float* __restrict__ b3,
                       float* __restrict__ out, int N, int C) {
    __shared__ float ges[HID], ces[HID], x1[HID], x2[64];
    int c = blockIdx.x, col = threadIdx.x;
    ges[col] = g_ge[col];
    ces[col] = g_ce[c * HID + col];
    __syncthreads();
    float acc = b1[col];
    for (int k = 0; k < HID; ++k) acc += ges[k] * w1[k * HID + col];
    for (int k = 0; k < HID; ++k) acc += ces[k] * w1[(HID + k) * HID + col];
    x1[col] = gelu_f(acc);
    __syncthreads();
    if (col < 64) {
        float a2 = b2[col];
        for (int k = 0; k < HID; ++k) a2 += x1[k] * w2[k * 64 + col];
        x2[col] = gelu_f(a2);
    }
    __syncthreads();
    if (col == 0) {
        float s = b3[0];
        for (int k = 0; k < 64; ++k) s += x2[k] * w3[k];
        out[c] = s;
    }
}

extern "C" void kernel_launch(void* const* d_in, const int* in_sizes, int n_in,
                              void* d_out, int out_size) {
    const float* node_feat = (const float*)d_in[0];
    const int*   node_opc  = (const int*)d_in[1];
    const float* topo      = (const float*)d_in[2];
    const int*   ei        = (const int*)d_in[3];
    const int*   cfg_ids   = (const int*)d_in[4];
    const float* cfg_feat  = (const float*)d_in[5];
    const float* temp      = (const float*)d_in[6];
    const float* opc_emb   = (const float*)d_in[7];
    const float* in_w      = (const float*)d_in[8];
    const float* in_b      = (const float*)d_in[9];
    const float* in_g      = (const float*)d_in[10];
    const float* in_beta   = (const float*)d_in[11];
    const float* sage_Wl   = (const float*)d_in[12];
    const float* sage_bl   = (const float*)d_in[13];
    const float* sage_Wr   = (const float*)d_in[14];
    const float* ln_g      = (const float*)d_in[15];
    const float* ln_b      = (const float*)d_in[16];
    const float* cfg_w     = (const float*)d_in[17];
    const float* cfg_b     = (const float*)d_in[18];
    const float* se_w1     = (const float*)d_in[19];
    const float* se_b1     = (const float*)d_in[20];
    const float* se_w2     = (const float*)d_in[21];
    const float* se_b2     = (const float*)d_in[22];
    const float* h_w1      = (const float*)d_in[23];
    const float* h_b1      = (const float*)d_in[24];
    const float* h_w2      = (const float*)d_in[25];
    const float* h_b2      = (const float*)d_in[26];
    const float* h_w3      = (const float*)d_in[27];
    const float* h_b3      = (const float*)d_in[28];

    int N  = in_sizes[1];
    int M  = in_sizes[3] / 2;
    int NC = in_sizes[4];
    int C  = in_sizes[5] / (NC * 18);
    int chunks = C / CH;
    int nblk = (N + 63) / 64;

    size_t in_smem = (size_t)205 * XSTR * 4;
    size_t ly_smem = (size_t)256 * XSTR * 4;
    cudaFuncSetAttribute(k_input, cudaFuncAttributeMaxDynamicSharedMemorySize, (int)in_smem);
    cudaFuncSetAttribute(k_layer, cudaFuncAttributeMaxDynamicSharedMemorySize, (int)ly_smem);

    k_zero<<<(N + 255) / 256, 256>>>(N);
    k_input<<<nblk, 256, in_smem>>>(node_feat, node_opc, topo, opc_emb,
                                    in_w, in_b, in_g, in_beta, N);
    k_deg<<<(M + 255) / 256, 256>>>(ei, M);
    int sb = (N + 1023) / 1024;
    k_scan1<<<sb, 1024>>>(N);
    k_scan2<<<1, 32>>>(sb);
    k_scan3<<<(N + 255) / 256, 256>>>(N);
    k_posinv<<<(N + 255) / 256, 256>>>(N);
    k_scatter<<<(M + 255) / 256, 256>>>(ei, M);
    for (int l = 0; l < 4; ++l) {
        k_agg<<<(N + 7) / 8, 256>>>(N);
        k_layer<<<nblk, 256, ly_smem>>>(sage_Wl + (size_t)l * HID * HID,
                                        sage_bl + l * HID,
                                        sage_Wr + (size_t)l * HID * HID,
                                        ln_g + l * HID, ln_b + l * HID, N);
    }
    k_gmean1<<<512, 128>>>(N);
    k_gmean2<<<1, 128>>>(N);
    k_base<<<NC, 128>>>(cfg_ids, cfg_w, cfg_b, NC);

    size_t score_smem = (size_t)CH * HID * 2 +
                        (HID + 18 * HID + HID * 16 + 16 * HID + 16 + HID) * sizeof(float);
    cudaFuncSetAttribute(k_score, cudaFuncAttributeMaxDynamicSharedMemorySize, (int)score_smem);
    dim3 sg(chunks, NC);
    k_score<<<sg, CH, score_smem>>>(cfg_feat, cfg_w, se_w1, se_b1, se_w2, se_b2,
                                    temp, C, NC);
    k_reduce<<<C, 128>>>(C, NC);
    k_head<<<C, 128>>>(h_w1, h_b1, h_w2, h_b2, h_w3, h_b3, (float*)d_out, N, C);
}

// round 6
// speedup vs baseline: 1.3766x; 1.0452x over previous
#include <cuda_runtime.h>
#include <cuda_fp16.h>
#include <cstdint>
#include <cstddef>

#define HID 128
#define NMAX 100000
#define MMAX 800000
#define CMAX 1024
#define NCMAX 1000
#define CH 512
#define XSTR 68   // smem row stride (floats) for transposed x tiles

typedef unsigned long long u64;

__device__ int    g_deg[NMAX];
__device__ int    g_rowstart[NMAX + 1];
__device__ int    g_pos[NMAX];
__device__ float  g_invdeg[NMAX];
__device__ int    g_csr[MMAX];
__device__ int    g_bsum[128];
__device__ int    g_boff[128];
__device__ float  g_h[(size_t)NMAX * HID];
__device__ float  g_agg[(size_t)NMAX * HID];
__device__ float  g_base[NCMAX * HID];
__device__ float  g_partial[512 * HID];
__device__ float  g_ge[HID];
__device__ float  g_ce[CMAX * HID];
__device__ __half g_slab[(size_t)CMAX * NCMAX * HID];

__device__ __forceinline__ float gelu_f(float x) {
    return 0.5f * x * (1.0f + erff(x * 0.70710678f));
}
__device__ __forceinline__ float wred(float v) {
    #pragma unroll
    for (int o = 16; o; o >>= 1) v += __shfl_xor_sync(0xffffffffu, v, o);
    return v;
}
__device__ __forceinline__ u64 dup2(float a) {
    u64 r;
    asm("mov.b64 %0, {%1, %1};" : "=l"(r) : "f"(a));
    return r;
}
__device__ __forceinline__ void fma2(u64& d, u64 a, u64 b) {
    asm("fma.rn.f32x2 %0, %1, %2, %0;" : "+l"(d) : "l"(a), "l"(b));
}
__device__ __forceinline__ float2 unpk(u64 v) {
    float2 r;
    asm("mov.b64 {%0, %1}, %2;" : "=f"(r.x), "=f"(r.y) : "l"(v));
    return r;
}

// ---------------- graph prep ----------------
__global__ void k_zero(int N) {
    int i = blockIdx.x * blockDim.x + threadIdx.x;
    if (i < N) g_deg[i] = 0;
}
__global__ void k_deg(const int* __restrict__ ei, int M) {
    int e = blockIdx.x * blockDim.x + threadIdx.x;
    if (e < M) atomicAdd(&g_deg[ei[M + e]], 1);
}
__global__ void k_scan1(int N) {
    __shared__ int s[1024];
    int t = threadIdx.x, i = blockIdx.x * 1024 + t;
    s[t] = (i < N) ? g_deg[i] : 0;
    __syncthreads();
    for (int o = 1; o < 1024; o <<= 1) {
        int a = (t >= o) ? s[t - o] : 0;
        __syncthreads();
        s[t] += a;
        __syncthreads();
    }
    if (i < N) g_rowstart[i + 1] = s[t];
    if (t == 1023) g_bsum[blockIdx.x] = s[1023];
}
__global__ void k_scan2(int nb) {
    if (threadIdx.x == 0) {
        int run = 0;
        for (int b = 0; b < nb; ++b) { g_boff[b] = run; run += g_bsum[b]; }
    }
}
__global__ void k_scan3(int N) {
    int i = blockIdx.x * blockDim.x + threadIdx.x;
    if (i == 0) g_rowstart[0] = 0;
    if (i < N) g_rowstart[i + 1] += g_boff[i >> 10];
}
__global__ void k_posinv(int N) {
    int i = blockIdx.x * blockDim.x + threadIdx.x;
    if (i < N) {
        g_pos[i] = g_rowstart[i];
        int d = g_deg[i];
        g_invdeg[i] = 1.0f / (float)(d > 0 ? d : 1);
    }
}
__global__ void k_scatter(const int* __restrict__ ei, int M) {
    int e = blockIdx.x * blockDim.x + threadIdx.x;
    if (e < M) {
        int dst = ei[M + e];
        int slot = atomicAdd(&g_pos[dst], 1);
        g_csr[slot] = ei[e];
    }
}

// ---------------- input embed: 64 nodes x 128 cols tiled GEMM (f32x2) + LN + GELU ----------------
__global__ void k_input(const float* __restrict__ feat, const int* __restrict__ opcode,
                        const float* __restrict__ depth, const float* __restrict__ emb,
                        const float* __restrict__ W, const float* __restrict__ b,
                        const float* __restrict__ lg, const float* __restrict__ lb, int N) {
    extern __shared__ float xs[];   // [205][XSTR] transposed: xs[k*XSTR + n]
    int tid = threadIdx.x, lane = tid & 31, wp = tid >> 5;
    int n0 = blockIdx.x * 64;
    for (int i = tid; i < 64 * 140; i += 256) {
        int n = i / 140, k = i - n * 140;
        int gn = n0 + n; if (gn >= N) gn = N - 1;
        xs[k * XSTR + n] = feat[(size_t)gn * 140 + k];
    }
    for (int i = tid; i < 64 * 64; i += 256) {
        int n = i >> 6, k = i & 63;
        int gn = n0 + n; if (gn >= N) gn = N - 1;
        int op = opcode[gn]; op = op < 0 ? 0 : (op > 119 ? 119 : op);
        xs[(140 + k) * XSTR + n] = emb[op * 64 + k];
    }
    if (tid < 64) {
        int gn = n0 + tid; if (gn >= N) gn = N - 1;
        xs[204 * XSTR + tid] = depth[gn];
    }
    __syncthreads();

    int ng = wp, c0 = lane * 4;
    u64 acc2[4][4];                 // [node pair][col], f32x2 = (node 2p, node 2p+1)
    #pragma unroll
    for (int p = 0; p < 4; ++p)
        #pragma unroll
        for (int c = 0; c < 4; ++c) acc2[p][c] = 0ull;
    #pragma unroll 2
    for (int k = 0; k < 205; ++k) {
        float4 w4 = *(const float4*)&W[k * HID + c0];
        u64 wd[4] = {dup2(w4.x), dup2(w4.y), dup2(w4.z), dup2(w4.w)};
        const u64* xp = (const u64*)&xs[k * XSTR + ng * 8];
        u64 xv[4] = {xp[0], xp[1], xp[2], xp[3]};
        #pragma unroll
        for (int p = 0; p < 4; ++p)
            #pragma unroll
            for (int c = 0; c < 4; ++c) fma2(acc2[p][c], xv[p], wd[c]);
    }
    float av[8][4];
    #pragma unroll
    for (int p = 0; p < 4; ++p)
        #pragma unroll
        for (int c = 0; c < 4; ++c) {
            float2 t = unpk(acc2[p][c]);
            av[2 * p][c] = t.x; av[2 * p + 1][c] = t.y;
        }
    float4 b4 = *(const float4*)&b[c0];
    float4 g4 = *(const float4*)&lg[c0];
    float4 e4 = *(const float4*)&lb[c0];
    float mu[8], iv[8];
    #pragma unroll
    for (int j = 0; j < 8; ++j) {
        av[j][0] += b4.x; av[j][1] += b4.y; av[j][2] += b4.z; av[j][3] += b4.w;
        mu[j] = wred(av[j][0] + av[j][1] + av[j][2] + av[j][3]) * (1.f / HID);
    }
    #pragma unroll
    for (int j = 0; j < 8; ++j) {
        float dx = av[j][0] - mu[j], dy = av[j][1] - mu[j];
        float dz = av[j][2] - mu[j], dw = av[j][3] - mu[j];
        iv[j] = rsqrtf(wred(dx * dx + dy * dy + dz * dz + dw * dw) * (1.f / HID) + 1e-5f);
    }
    #pragma unroll
    for (int j = 0; j < 8; ++j) {
        int gn = n0 + ng * 8 + j;
        if (gn < N) {
            float4 o;
            o.x = gelu_f((av[j][0] - mu[j]) * iv[j] * g4.x + e4.x);
            o.y = gelu_f((av[j][1] - mu[j]) * iv[j] * g4.y + e4.y);
            o.z = gelu_f((av[j][2] - mu[j]) * iv[j] * g4.z + e4.z);
            o.w = gelu_f((av[j][3] - mu[j]) * iv[j] * g4.w + e4.w);
            *(float4*)&g_h[(size_t)gn * HID + c0] = o;
        }
    }
}

// ---------------- mean aggregation: warp per node ----------------
__global__ void k_agg(int N) {
    int gw = (blockIdx.x * blockDim.x + threadIdx.x) >> 5;
    int lane = threadIdx.x & 31;
    if (gw >= N) return;
    int rs = g_rowstart[gw], re = g_rowstart[gw + 1];
    float4 acc = make_float4(0.f, 0.f, 0.f, 0.f);
    for (int e = rs; e < re; ++e) {
        int s = g_csr[e];
        float4 v = *(const float4*)&g_h[(size_t)s * HID + lane * 4];
        acc.x += v.x; acc.y += v.y; acc.z += v.z; acc.w += v.w;
    }
    float idg = g_invdeg[gw];
    acc.x *= idg; acc.y *= idg; acc.z *= idg; acc.w *= idg;
    *(float4*)&g_agg[(size_t)gw * HID + lane * 4] = acc;
}

// ---------------- SAGE layer: tiled GEMM (f32x2) + residual + LN ----------------
__global__ void k_layer(const float* __restrict__ Wl, const float* __restrict__ bl,
                        const float* __restrict__ Wr, const float* __restrict__ lg,
                        const float* __restrict__ lb, int N) {
    extern __shared__ float xs[];   // [256][XSTR]: rows 0..127 agg, 128..255 h
    int tid = threadIdx.x, lane = tid & 31, wp = tid >> 5;
    int n0 = blockIdx.x * 64;
    for (int i = tid; i < 64 * 128; i += 256) {
        int n = i >> 7, k = i & 127;
        int gn = n0 + n; if (gn >= N) gn = N - 1;
        xs[k * XSTR + n] = g_agg[(size_t)gn * HID + k];
        xs[(128 + k) * XSTR + n] = g_h[(size_t)gn * HID + k];
    }
    __syncthreads();

    int ng = wp, c0 = lane * 4;
    u64 acc2[4][4];
    #pragma unroll
    for (int p = 0; p < 4; ++p)
        #pragma unroll
        for (int c = 0; c < 4; ++c) acc2[p][c] = 0ull;
    #pragma unroll 2
    for (int k = 0; k < 128; ++k) {
        float4 w4 = *(const float4*)&Wl[k * HID + c0];
        u64 wd[4] = {dup2(w4.x), dup2(w4.y), dup2(w4.z), dup2(w4.w)};
        const u64* xp = (const u64*)&xs[k * XSTR + ng * 8];
        u64 xv[4] = {xp[0], xp[1], xp[2], xp[3]};
        #pragma unroll
        for (int p = 0; p < 4; ++p)
            #pragma unroll
            for (int c = 0; c < 4; ++c) fma2(acc2[p][c], xv[p], wd[c]);
    }
    #pragma unroll 2
    for (int k = 0; k < 128; ++k) {
        float4 w4 = *(const float4*)&Wr[k * HID + c0];
        u64 wd[4] = {dup2(w4.x), dup2(w4.y), dup2(w4.z), dup2(w4.w)};
        const u64* xp = (const u64*)&xs[(128 + k) * XSTR + ng * 8];
        u64 xv[4] = {xp[0], xp[1], xp[2], xp[3]};
        #pragma unroll
        for (int p = 0; p < 4; ++p)
            #pragma unroll
            for (int c = 0; c < 4; ++c) fma2(acc2[p][c], xv[p], wd[c]);
    }
    float av[8][4];
    #pragma unroll
    for (int p = 0; p < 4; ++p)
        #pragma unroll
        for (int c = 0; c < 4; ++c) {
            float2 t = unpk(acc2[p][c]);
            av[2 * p][c] = t.x; av[2 * p + 1][c] = t.y;
        }
    float4 b4 = *(const float4*)&bl[c0];
    float4 g4 = *(const float4*)&lg[c0];
    float4 e4 = *(const float4*)&lb[c0];
    float mu[8], iv[8];
    #pragma unroll
    for (int j = 0; j < 8; ++j) {
        int gn = n0 + ng * 8 + j; int cg = gn < N ? gn : N - 1;
        float4 hv = *(const float4*)&g_h[(size_t)cg * HID + c0];
        av[j][0] = hv.x + gelu_f(av[j][0] + b4.x);
        av[j][1] = hv.y + gelu_f(av[j][1] + b4.y);
        av[j][2] = hv.z + gelu_f(av[j][2] + b4.z);
        av[j][3] = hv.w + gelu_f(av[j][3] + b4.w);
        mu[j] = wred(av[j][0] + av[j][1] + av[j][2] + av[j][3]) * (1.f / HID);
    }
    #pragma unroll
    for (int j = 0; j < 8; ++j) {
        float dx = av[j][0] - mu[j], dy = av[j][1] - mu[j];
        float dz = av[j][2] - mu[j], dw = av[j][3] - mu[j];
        iv[j] = rsqrtf(wred(dx * dx + dy * dy + dz * dz + dw * dw) * (1.f / HID) + 1e-5f);
    }
    __syncthreads();   // all xs h-reads done before overwriting g_h
    #pragma unroll
    for (int j = 0; j < 8; ++j) {
        int gn = n0 + ng * 8 + j;
        if (gn < N) {
            float4 o;
            o.x = (av[j][0] - mu[j]) * iv[j] * g4.x + e4.x;
            o.y = (av[j][1] - mu[j]) * iv[j] * g4.y + e4.y;
            o.z = (av[j][2] - mu[j]) * iv[j] * g4.z + e4.z;
            o.w = (av[j][3] - mu[j]) * iv[j] * g4.w + e4.w;
            *(float4*)&g_h[(size_t)gn * HID + c0] = o;
        }
    }
}

// ---------------- global mean of h (deterministic 2-stage) ----------------
__global__ void k_gmean1(int N) {
    int col = threadIdx.x, blk = blockIdx.x;
    int per = (N + 511) / 512;
    int a = blk * per, b = a + per; if (b > N) b = N;
    float acc = 0.f;
    for (int n = a; n < b; ++n) acc += g_h[(size_t)n * HID + col];
    g_partial[blk * HID + col] = acc;
}
__global__ void k_gmean2(int N) {
    int col = threadIdx.x;
    float acc = 0.f;
    for (int b = 0; b < 512; ++b) acc += g_partial[b * HID + col];
    g_ge[col] = acc / (float)N;
}

// ---------------- base[nc] = h[cfg_id[nc]] @ cfg_w[:128] + cfg_b ----------------
__global__ void k_base(const int* __restrict__ ids, const float* __restrict__ W,
                       const float* __restrict__ b, int NC) {
    __shared__ float row[HID];
    int nc = blockIdx.x, col = threadIdx.x;
    int nd = ids[nc];
    row[col] = g_h[(size_t)nd * HID + col];
    __syncthreads();
    float acc = b[col];
    for (int k = 0; k < HID; ++k) acc += row[k] * W[k * HID + col];
    g_base[nc * HID + col] = acc;
}

// ---------------- scoring: proj + SE + chunk softmax (f32x2 col-pairs) ----------------
__global__ void k_score(const float* __restrict__ cfgf, const float* __restrict__ cfg_w,
                        const float* __restrict__ w1, const float* __restrict__ b1,
                        const float* __restrict__ w2s, const float* __restrict__ b2,
                        const float* __restrict__ temp, int C, int NC) {
    extern __shared__ unsigned char sm[];
    __half* projs = (__half*)sm;                       // 512*128
    float* base_s = (float*)(sm + CH * HID * 2);       // 128
    float* w18 = base_s + HID;                         // 18*128
    float* sw1 = w18 + 18 * HID;                       // 128*16
    float* sw2 = sw1 + HID * 16;                       // 16*128
    float* sb1 = sw2 + 16 * HID;                       // 16
    float* sb2 = sb1 + 16;                             // 128
    int tid = threadIdx.x;
    int chunk = blockIdx.x, nc = blockIdx.y;
    for (int i = tid; i < 18 * HID; i += CH) w18[i] = cfg_w[128 * HID + i];
    for (int i = tid; i < HID * 16; i += CH) sw1[i] = w1[i];
    for (int i = tid; i < 16 * HID; i += CH) sw2[i] = w2s[i];
    if (tid < 16) sb1[tid] = b1[tid];
    if (tid < HID) sb2[tid] = b2[tid];
    if (tid < HID) base_s[tid] = g_base[nc * HID + tid];
    __syncthreads();
    int c = tid;
    int cg = chunk * CH + c;
    u64 fd[18];
    #pragma unroll
    for (int j = 0; j < 18; ++j) fd[j] = dup2(cfgf[((size_t)cg * NC + nc) * 18 + j]);
    u64 s12[8];
    #pragma unroll
    for (int r = 0; r < 8; ++r) s12[r] = *(const u64*)&sb1[r * 2];
    for (int col = 0; col < HID; col += 2) {
        u64 v2 = *(const u64*)&base_s[col];
        #pragma unroll
        for (int j = 0; j < 18; ++j) fma2(v2, fd[j], *(const u64*)&w18[j * HID + col]);
        float2 vv = unpk(v2);
        float va = gelu_f(vv.x), vb = gelu_f(vv.y);
        projs[col * CH + c] = __float2half(va);
        projs[(col + 1) * CH + c] = __float2half(vb);
        u64 vda = dup2(va), vdb = dup2(vb);
        #pragma unroll
        for (int r = 0; r < 8; ++r) {
            fma2(s12[r], vda, *(const u64*)&sw1[col * 16 + r * 2]);
            fma2(s12[r], vdb, *(const u64*)&sw1[(col + 1) * 16 + r * 2]);
        }
    }
    u64 s1d[16];
    #pragma unroll
    for (int r = 0; r < 8; ++r) {
        float2 t = unpk(s12[r]);
        s1d[2 * r] = dup2(fmaxf(t.x, 0.f));
        s1d[2 * r + 1] = dup2(fmaxf(t.y, 0.f));
    }
    for (int col = 0; col < HID; col += 2) {
        u64 z2 = *(const u64*)&sb2[col];
        #pragma unroll
        for (int r = 0; r < 16; ++r) fma2(z2, s1d[r], *(const u64*)&sw2[r * HID + col]);
        float2 zz = unpk(z2);
        float sa = 1.f / (1.f + __expf(-zz.x));
        float sb_ = 1.f / (1.f + __expf(-zz.y));
        projs[col * CH + c] = __float2half(__half2float(projs[col * CH + c]) * sa);
        projs[(col + 1) * CH + c] = __float2half(__half2float(projs[(col + 1) * CH + c]) * sb_);
    }
    __syncthreads();
    float invT = 1.f / temp[0];
    int lane = tid & 31, wid = tid >> 5;
    for (int ci = 0; ci < 8; ++ci) {
        int col = wid + ci * 16;
        float v[16], m = -1e30f;
        #pragma unroll
        for (int i = 0; i < 16; ++i) {
            v[i] = __half2float(projs[col * CH + lane + i * 32]);
            m = fmaxf(m, v[i]);
        }
        #pragma unroll
        for (int o = 16; o; o >>= 1) m = fmaxf(m, __shfl_xor_sync(0xffffffffu, m, o));
        float se = 0.f;
        #pragma unroll
        for (int i = 0; i < 16; ++i) se += __expf((v[i] - m) * invT);
        se = wred(se);
        float inv_se = 1.f / se;
        #pragma unroll
        for (int i = 0; i < 16; ++i) {
            float w = __expf((v[i] - m) * invT) * inv_se;
            projs[col * CH + lane + i * 32] = __float2half(v[i] * w);
        }
    }
    __syncthreads();
    for (int i = tid; i < CH * HID; i += CH) {
        int cl = i >> 7, col = i & 127;
        g_slab[((size_t)(chunk * CH + cl) * NC + nc) * HID + col] = projs[col * CH + cl];
    }
}

// ---------------- slab reduce: config_embeds = mean over nc (vectorized) ----------------
__global__ void k_reduce(int C, int NC) {
    __shared__ float red[8][HID];
    int c = blockIdx.x, tid = threadIdx.x;
    int cg = (tid & 15) * 8, rg = tid >> 4;
    float a[8];
    #pragma unroll
    for (int i = 0; i < 8; ++i) a[i] = 0.f;
    for (int nc = rg; nc < NC; nc += 8) {
        uint4 v = *(const uint4*)&g_slab[((size_t)c * NC + nc) * HID + cg];
        const __half2* h2 = (const __half2*)&v;
        #pragma unroll
        for (int i = 0; i < 4; ++i) {
            float2 f = __half22float2(h2[i]);
            a[2 * i] += f.x; a[2 * i + 1] += f.y;
        }
    }
    #pragma unroll
    for (int i = 0; i < 8; ++i) red[rg][cg + i] = a[i];
    __syncthreads();
    if (tid < HID) {
        float s = 0.f;
        #pragma unroll
        for (int r = 0; r < 8; ++r) s += red[r][tid];
        g_ce[c * HID + tid] = s / (float)NC;
    }
}

// ---------------- head MLP ----------------
__global__ void k_head(const float* __restrict__ w1, const float* __restrict__ b1,
                       const float* __restrict__ w2, const float* __restrict__ b2,
                       const float* __restrict__ w3, const float* __restrict__ b3,
                       float* __restrict__ out, int N, int C) {
    __shared__ float ges[HID], ces[HID], x1[HID], x2[64];
    int c = blockIdx.x, col = threadIdx.x;
    ges[col] = g_ge[col];
    ces[col] = g_ce[c * HID + col];
    __syncthreads();
    float acc = b1[col];
    for (int k = 0; k < HID; ++k) acc += ges[k] * w1[k * HID + col];
    for (int k = 0; k < HID; ++k) acc += ces[k] * w1[(HID + k) * HID + col];
    x1[col] = gelu_f(acc);
    __syncthreads();
    if (col < 64) {
        float a2 = b2[col];
        for (int k = 0; k < HID; ++k) a2 += x1[k] * w2[k * 64 + col];
        x2[col] = gelu_f(a2);
    }
    __syncthreads();
    if (col == 0) {
        float s = b3[0];
        for (int k = 0; k < 64; ++k) s += x2[k] * w3[k];
        out[c] = s;
    }
}

extern "C" void kernel_launch(void* const* d_in, const int* in_sizes, int n_in,
                              void* d_out, int out_size) {
    const float* node_feat = (const float*)d_in[0];
    const int*   node_opc  = (const int*)d_in[1];
    const float* topo      = (const float*)d_in[2];
    const int*   ei        = (const int*)d_in[3];
    const int*   cfg_ids   = (const int*)d_in[4];
    const float* cfg_feat  = (const float*)d_in[5];
    const float* temp      = (const float*)d_in[6];
    const float* opc_emb   = (const float*)d_in[7];
    const float* in_w      = (const float*)d_in[8];
    const float* in_b      = (const float*)d_in[9];
    const float* in_g      = (const float*)d_in[10];
    const float* in_beta   = (const float*)d_in[11];
    const float* sage_Wl   = (const float*)d_in[12];
    const float* sage_bl   = (const float*)d_in[13];
    const float* sage_Wr   = (const float*)d_in[14];
    const float* ln_g      = (const float*)d_in[15];
    const float* ln_b      = (const float*)d_in[16];
    const float* cfg_w     = (const float*)d_in[17];
    const float* cfg_b     = (const float*)d_in[18];
    const float* se_w1     = (const float*)d_in[19];
    const float* se_b1     = (const float*)d_in[20];
    const float* se_w2     = (const float*)d_in[21];
    const float* se_b2     = (const float*)d_in[22];
    const float* h_w1      = (const float*)d_in[23];
    const float* h_b1      = (const float*)d_in[24];
    const float* h_w2      = (const float*)d_in[25];
    const float* h_b2      = (const float*)d_in[26];
    const float* h_w3      = (const float*)d_in[27];
    const float* h_b3      = (const float*)d_in[28];

    int N  = in_sizes[1];
    int M  = in_sizes[3] / 2;
    int NC = in_sizes[4];
    int C  = in_sizes[5] / (NC * 18);
    int chunks = C / CH;
    int nblk = (N + 63) / 64;

    size_t in_smem = (size_t)205 * XSTR * 4;
    size_t ly_smem = (size_t)256 * XSTR * 4;
    cudaFuncSetAttribute(k_input, cudaFuncAttributeMaxDynamicSharedMemorySize, (int)in_smem);
    cudaFuncSetAttribute(k_layer, cudaFuncAttributeMaxDynamicSharedMemorySize, (int)ly_smem);

    k_zero<<<(N + 255) / 256, 256>>>(N);
    k_input<<<nblk, 256, in_smem>>>(node_feat, node_opc, topo, opc_emb,
                                    in_w, in_b, in_g, in_beta, N);
    k_deg<<<(M + 255) / 256, 256>>>(ei, M);
    int sb = (N + 1023) / 1024;
    k_scan1<<<sb, 1024>>>(N);
    k_scan2<<<1, 32>>>(sb);
    k_scan3<<<(N + 255) / 256, 256>>>(N);
    k_posinv<<<(N + 255) / 256, 256>>>(N);
    k_scatter<<<(M + 255) / 256, 256>>>(ei, M);
    for (int l = 0; l < 4; ++l) {
        k_agg<<<(N + 7) / 8, 256>>>(N);
        k_layer<<<nblk, 256, ly_smem>>>(sage_Wl + (size_t)l * HID * HID,
                                        sage_bl + l * HID,
                                        sage_Wr + (size_t)l * HID * HID,
                                        ln_g + l * HID, ln_b + l * HID, N);
    }
    k_gmean1<<<512, 128>>>(N);
    k_gmean2<<<1, 128>>>(N);
    k_base<<<NC, 128>>>(cfg_ids, cfg_w, cfg_b, NC);

    size_t score_smem = (size_t)CH * HID * 2 +
                        (HID + 18 * HID + HID * 16 + 16 * HID + 16 + HID) * sizeof(float);
    cudaFuncSetAttribute(k_score, cudaFuncAttributeMaxDynamicSharedMemorySize, (int)score_smem);
    dim3 sg(chunks, NC);
    k_score<<<sg, CH, score_smem>>>(cfg_feat, cfg_w, se_w1, se_b1, se_w2, se_b2,
                                    temp, C, NC);
    k_reduce<<<C, 128>>>(C, NC);
    k_head<<<C, 128>>>(h_w1, h_b1, h_w2, h_b2, h_w3, h_b3, (float*)d_out, N, C);
}